// round 6
// baseline (speedup 1.0000x reference)
#include <cuda_runtime.h>
#include <cstdint>
#include <cmath>

// FastAttention (FAVOR+ linear attention), pure fp32 scalar-FMA pipeline.
// Inputs (metadata order): qs[B,Q,128] f32, ks[B,K,128] f32, vs[B,K,128] f32,
//                          proj[128,128] f32, valid_lens[B] int (32 or 64 — sniffed).
// Output: out[B,Q,128] f32.

#define EPS_F 1e-6f
#define MAXB 8
#define LDP 132   // padded leading dim for transposed proj
#define ISM 0.08838834764831845f   // 1/sqrt(128)

// Scratch (device globals; no allocation allowed). Re-zeroed every launch.
__device__ float g_kv[MAXB * 128 * 128];
__device__ float g_ksum[MAXB * 128];

__global__ void zero_kernel() {
    int i = blockIdx.x * blockDim.x + threadIdx.x;
    if (i < MAXB * 128 * 128) g_kv[i] = 0.0f;
    if (i < MAXB * 128)       g_ksum[i] = 0.0f;
}

// Robust valid_lens read: the harness may deliver int32 (its documented int
// type) or int64 (the reference dtype). Sniff: int64 little-endian with
// values < 2^31 shows [v,0,v,0,...] as int32 words. Only reads the first
// 32 bytes for the sniff (safe under both layouts when B >= 4).
__device__ __forceinline__ long long read_vlen(const void* p, int b, int B) {
    const int* p32 = (const int*)p;
    bool is64;
    if (B >= 4) {
        is64 = (p32[1] == 0 && p32[3] == 0 && p32[5] == 0 && p32[7] == 0);
    } else {
        is64 = (p32[1] == 0);
    }
    if (is64) return ((const long long*)p)[b];
    return (long long)p32[b];
}

// ---------------------------------------------------------------------------
// Kernel 1: KV[m][v] = sum_k phi_k[k][m] * V[k][v], ksum[m] = sum_k phi_k[k][m]
// Block: 256 threads (16x16), 8x8 register tile each, TPB*128 K rows per block.
// ---------------------------------------------------------------------------
__global__ void __launch_bounds__(256, 1)
kv_kernel(const float* __restrict__ ks, const float* __restrict__ vs,
          const float* __restrict__ proj, const void* __restrict__ vlens,
          int Kdim, int tiles_per_block, float nrm, int B)
{
    extern __shared__ float smem[];
    float* Pt  = smem;                  // [128][LDP]  Pt[d][m] = proj[m][d]
    float* Xs  = Pt + 128 * LDP;        // [128][128]  scaled K tile, reused as phi
    float* Vs  = Xs + 128 * 128;        // [128][128]  V tile
    float* h_s = Vs + 128 * 128;        // [128]

    const int tid = threadIdx.x;
    const int b   = blockIdx.y;
    const int tx  = tid & 15, ty = tid >> 4;
    const int r0  = ty * 8;             // row block (m block for the KV output)
    const int c0  = tx * 8;             // col block
    const long long vlen = read_vlen(vlens, b, B);

    for (int idx = tid; idx < 128 * 128; idx += 256) {
        int m = idx >> 7, d = idx & 127;
        Pt[d * LDP + m] = proj[idx];
    }

    float kvacc[8][8];
    #pragma unroll
    for (int i = 0; i < 8; i++)
        #pragma unroll
        for (int j = 0; j < 8; j++) kvacc[i][j] = 0.0f;
    float ksum_loc = 0.0f;

    const int row_base = blockIdx.x * (tiles_per_block * 128);

    for (int t = 0; t < tiles_per_block; t++) {
        const int row0 = row_base + t * 128;
        const float* kp = ks + ((size_t)b * Kdim + row0) * 128;
        const float* vp = vs + ((size_t)b * Kdim + row0) * 128;
        for (int idx = tid; idx < 128 * 128; idx += 256) {
            Xs[idx] = kp[idx] * nrm;
            Vs[idx] = vp[idx];
        }
        __syncthreads();

        // h[r] = 0.5*||x_r||^2 (rotated column index: conflict-free)
        if (tid < 128) {
            float s = 0.0f;
            #pragma unroll 4
            for (int dd = 0; dd < 128; dd++) {
                float v = Xs[tid * 128 + ((dd + tid) & 127)];
                s = fmaf(v, v, s);
            }
            h_s[tid] = 0.5f * s;
        }

        // GEMM1: C[r][m] = sum_d Xs[r][d] * Pt[d][m]
        float cacc[8][8];
        #pragma unroll
        for (int i = 0; i < 8; i++)
            #pragma unroll
            for (int j = 0; j < 8; j++) cacc[i][j] = 0.0f;

        for (int d = 0; d < 128; d++) {
            float a[8];
            #pragma unroll
            for (int i = 0; i < 8; i++) a[i] = Xs[(r0 + i) * 128 + d];
            float4 b03 = *(const float4*)(Pt + d * LDP + c0);
            float4 b47 = *(const float4*)(Pt + d * LDP + c0 + 4);
            float bb[8] = {b03.x, b03.y, b03.z, b03.w, b47.x, b47.y, b47.z, b47.w};
            #pragma unroll
            for (int i = 0; i < 8; i++)
                #pragma unroll
                for (int j = 0; j < 8; j++)
                    cacc[i][j] = fmaf(a[i], bb[j], cacc[i][j]);
        }
        __syncthreads();   // all GEMM1 reads of Xs done

        // phi = exp(C - h)/sqrt(m), masked by valid length; store into Xs
        #pragma unroll
        for (int i = 0; i < 8; i++) {
            int r = r0 + i;
            bool valid = ((long long)(row0 + r) < vlen);
            float hr = h_s[r];
            float o[8];
            #pragma unroll
            for (int j = 0; j < 8; j++)
                o[j] = valid ? expf(cacc[i][j] - hr) * ISM : 0.0f;
            *(float4*)(Xs + r * 128 + c0)     = make_float4(o[0], o[1], o[2], o[3]);
            *(float4*)(Xs + r * 128 + c0 + 4) = make_float4(o[4], o[5], o[6], o[7]);
        }
        __syncthreads();

        // GEMM2: KV[m][v] += sum_r phi[r][m] * Vs[r][v]  (m block = r0, v block = c0)
        for (int r = 0; r < 128; r++) {
            float4 a03 = *(const float4*)(Xs + r * 128 + r0);
            float4 a47 = *(const float4*)(Xs + r * 128 + r0 + 4);
            float a[8] = {a03.x, a03.y, a03.z, a03.w, a47.x, a47.y, a47.z, a47.w};
            float4 b03 = *(const float4*)(Vs + r * 128 + c0);
            float4 b47 = *(const float4*)(Vs + r * 128 + c0 + 4);
            float bb[8] = {b03.x, b03.y, b03.z, b03.w, b47.x, b47.y, b47.z, b47.w};
            #pragma unroll
            for (int i = 0; i < 8; i++)
                #pragma unroll
                for (int j = 0; j < 8; j++)
                    kvacc[i][j] = fmaf(a[i], bb[j], kvacc[i][j]);
        }

        // ksum[m] partial: column sums of phi
        if (tid < 128) {
            float s = 0.0f;
            #pragma unroll 4
            for (int r = 0; r < 128; r++) s += Xs[r * 128 + tid];
            ksum_loc += s;
        }
        __syncthreads();   // before next tile overwrites Xs/Vs
    }

    float* kvb = g_kv + b * 128 * 128;
    #pragma unroll
    for (int i = 0; i < 8; i++)
        #pragma unroll
        for (int j = 0; j < 8; j++)
            atomicAdd(kvb + (r0 + i) * 128 + c0 + j, kvacc[i][j]);
    if (tid < 128) atomicAdd(g_ksum + b * 128 + tid, ksum_loc);
}

// ---------------------------------------------------------------------------
// Kernel 2: out[r][v] = (phi_q @ KV)[r][v] / max(phi_q . ksum, EPS)
// ---------------------------------------------------------------------------
__global__ void __launch_bounds__(256, 1)
out_kernel(const float* __restrict__ qs, const float* __restrict__ proj,
           float* __restrict__ out, int Qdim, float nrm)
{
    extern __shared__ float smem[];
    float* Pt     = smem;                   // [128][LDP]
    float* Xs     = Pt + 128 * LDP;         // [128][128]  Q tile -> phi
    float* KVs    = Xs + 128 * 128;         // [128][128]
    float* ksum_s = KVs + 128 * 128;        // [128]
    float* h_s    = ksum_s + 128;           // [128]
    float* den_s  = h_s + 128;              // [128]

    const int tid = threadIdx.x;
    const int b   = blockIdx.y;
    const int tx  = tid & 15, ty = tid >> 4;
    const int r0  = ty * 8;
    const int c0  = tx * 8;
    const int row0 = blockIdx.x * 128;

    for (int idx = tid; idx < 128 * 128; idx += 256) {
        int m = idx >> 7, d = idx & 127;
        Pt[d * LDP + m] = proj[idx];
        KVs[idx] = g_kv[b * 128 * 128 + idx];
    }
    if (tid < 128) ksum_s[tid] = g_ksum[b * 128 + tid];

    const float* qp = qs + ((size_t)b * Qdim + row0) * 128;
    for (int idx = tid; idx < 128 * 128; idx += 256)
        Xs[idx] = qp[idx] * nrm;
    __syncthreads();

    if (tid < 128) {
        float s = 0.0f;
        #pragma unroll 4
        for (int dd = 0; dd < 128; dd++) {
            float v = Xs[tid * 128 + ((dd + tid) & 127)];
            s = fmaf(v, v, s);
        }
        h_s[tid] = 0.5f * s;
    }

    // GEMM1: C[r][m] = sum_d Xs[r][d] * Pt[d][m]
    float cacc[8][8];
    #pragma unroll
    for (int i = 0; i < 8; i++)
        #pragma unroll
        for (int j = 0; j < 8; j++) cacc[i][j] = 0.0f;

    for (int d = 0; d < 128; d++) {
        float a[8];
        #pragma unroll
        for (int i = 0; i < 8; i++) a[i] = Xs[(r0 + i) * 128 + d];
        float4 b03 = *(const float4*)(Pt + d * LDP + c0);
        float4 b47 = *(const float4*)(Pt + d * LDP + c0 + 4);
        float bb[8] = {b03.x, b03.y, b03.z, b03.w, b47.x, b47.y, b47.z, b47.w};
        #pragma unroll
        for (int i = 0; i < 8; i++)
            #pragma unroll
            for (int j = 0; j < 8; j++)
                cacc[i][j] = fmaf(a[i], bb[j], cacc[i][j]);
    }
    __syncthreads();

    // phi (queries: no mask) -> Xs
    #pragma unroll
    for (int i = 0; i < 8; i++) {
        int r = r0 + i;
        float hr = h_s[r];
        float o[8];
        #pragma unroll
        for (int j = 0; j < 8; j++)
            o[j] = expf(cacc[i][j] - hr) * ISM;
        *(float4*)(Xs + r * 128 + c0)     = make_float4(o[0], o[1], o[2], o[3]);
        *(float4*)(Xs + r * 128 + c0 + 4) = make_float4(o[4], o[5], o[6], o[7]);
    }
    __syncthreads();

    // den[r] = sum_m phi[r][m] * ksum[m]
    if (tid < 128) {
        float s = 0.0f;
        #pragma unroll 4
        for (int mm = 0; mm < 128; mm++) {
            int m = (mm + tid) & 127;
            s = fmaf(Xs[tid * 128 + m], ksum_s[m], s);
        }
        den_s[tid] = fmaxf(s, EPS_F);
    }

    // GEMM3: O[r][v] = sum_m phi[r][m] * KVs[m][v]
    float oacc[8][8];
    #pragma unroll
    for (int i = 0; i < 8; i++)
        #pragma unroll
        for (int j = 0; j < 8; j++) oacc[i][j] = 0.0f;

    for (int m = 0; m < 128; m++) {
        float a[8];
        #pragma unroll
        for (int i = 0; i < 8; i++) a[i] = Xs[(r0 + i) * 128 + m];
        float4 b03 = *(const float4*)(KVs + m * 128 + c0);
        float4 b47 = *(const float4*)(KVs + m * 128 + c0 + 4);
        float bb[8] = {b03.x, b03.y, b03.z, b03.w, b47.x, b47.y, b47.z, b47.w};
        #pragma unroll
        for (int i = 0; i < 8; i++)
            #pragma unroll
            for (int j = 0; j < 8; j++)
                oacc[i][j] = fmaf(a[i], bb[j], oacc[i][j]);
    }
    __syncthreads();   // den_s visible to all

    #pragma unroll
    for (int i = 0; i < 8; i++) {
        int r = r0 + i;
        float inv = 1.0f / den_s[r];
        float* op = out + ((size_t)b * Qdim + row0 + r) * 128 + c0;
        *(float4*)op = make_float4(oacc[i][0] * inv, oacc[i][1] * inv,
                                   oacc[i][2] * inv, oacc[i][3] * inv);
        *(float4*)(op + 4) = make_float4(oacc[i][4] * inv, oacc[i][5] * inv,
                                         oacc[i][6] * inv, oacc[i][7] * inv);
    }
}

extern "C" void kernel_launch(void* const* d_in, const int* in_sizes, int n_in,
                              void* d_out, int out_size)
{
    const float* qs    = (const float*)d_in[0];
    const float* ks    = (const float*)d_in[1];
    const float* vs    = (const float*)d_in[2];
    const float* proj  = (const float*)d_in[3];
    const void*  vlens = (const void*)d_in[4];

    const int B = in_sizes[4];
    const int D = 128;
    const int Q = in_sizes[0] / (B * D);
    const int K = in_sizes[1] / (B * D);
    const float nrm = 1.0f / powf((float)D, 0.25f);

    const size_t smem1 = (size_t)(128 * LDP + 2 * 128 * 128 + 128) * sizeof(float);
    const size_t smem2 = (size_t)(128 * LDP + 2 * 128 * 128 + 3 * 128) * sizeof(float);
    cudaFuncSetAttribute(kv_kernel,  cudaFuncAttributeMaxDynamicSharedMemorySize, (int)smem1);
    cudaFuncSetAttribute(out_kernel, cudaFuncAttributeMaxDynamicSharedMemorySize, (int)smem2);

    zero_kernel<<<(MAXB * 128 * 128 + 255) / 256, 256>>>();

    const int TPB = 4;  // 512 K-rows per block -> 16 blocks/batch * 8 batches = 128 CTAs
    dim3 g1(K / (TPB * 128), B);
    kv_kernel<<<g1, 256, smem1>>>(ks, vs, proj, vlens, K, TPB, nrm, B);

    dim3 g2(Q / 128, B);
    out_kernel<<<g2, 256, smem2>>>(qs, proj, (float*)d_out, Q, nrm);
}

// round 15
// speedup vs baseline: 1.2211x; 1.2211x over previous
#include <cuda_runtime.h>
#include <cstdint>
#include <cmath>

// FastAttention (FAVOR+ linear attention), packed f32x2 (FFMA2) + __expf pipeline.
// Inputs (metadata order): qs[B,Q,128] f32, ks[B,K,128] f32, vs[B,K,128] f32,
//                          proj[128,128] f32, valid_lens[B] int (32/64 sniffed).
// Output: out[B,Q,128] f32.

#define EPS_F 1e-6f
#define MAXB 8
#define LDP 132
#define ISM 0.08838834764831845f   // 1/sqrt(128)

typedef unsigned long long u64;

__device__ float g_kv[MAXB * 128 * 128];
__device__ float g_ksum[MAXB * 128];

__global__ void zero_kernel() {
    int i = blockIdx.x * blockDim.x + threadIdx.x;
    if (i < MAXB * 128 * 128) g_kv[i] = 0.0f;
    if (i < MAXB * 128)       g_ksum[i] = 0.0f;
}

// Packed fp32 pair helpers (sm_103a FFMA2 path; ptxas never auto-fuses).
__device__ __forceinline__ u64 pack2(float x) {
    u64 r; unsigned b = __float_as_uint(x);
    asm("mov.b64 %0, {%1, %1};" : "=l"(r) : "r"(b));
    return r;
}
__device__ __forceinline__ void fma2(u64 &d, u64 a, u64 b) {
    asm("fma.rn.f32x2 %0, %1, %2, %0;" : "+l"(d) : "l"(a), "l"(b));
}
__device__ __forceinline__ float2 unpack2(u64 v) {
    unsigned lo, hi;
    asm("mov.b64 {%0, %1}, %2;" : "=r"(lo), "=r"(hi) : "l"(v));
    return make_float2(__uint_as_float(lo), __uint_as_float(hi));
}

// Robust valid_lens read (harness may deliver int32 or int64; sniff layout).
__device__ __forceinline__ long long read_vlen(const void* p, int b, int B) {
    const int* p32 = (const int*)p;
    bool is64;
    if (B >= 4) is64 = (p32[1] == 0 && p32[3] == 0 && p32[5] == 0 && p32[7] == 0);
    else        is64 = (p32[1] == 0);
    if (is64) return ((const long long*)p)[b];
    return (long long)p32[b];
}

// ---------------------------------------------------------------------------
// Kernel 1: KV[m][v] = sum_k phi_k[k][m]*V[k][v], ksum[m] = sum_k phi_k[k][m]
// 256 threads (16x16), 8x8 tile per thread as 8x4 packed pairs.
// ---------------------------------------------------------------------------
__global__ void __launch_bounds__(256, 1)
kv_kernel(const float* __restrict__ ks, const float* __restrict__ vs,
          const float* __restrict__ proj, const void* __restrict__ vlens,
          int Kdim, int tiles_per_block, float nrm, int B)
{
    extern __shared__ float smem[];
    float* Pt  = smem;                  // [128][LDP]  Pt[d][m] = proj[m][d]
    float* Xs  = Pt + 128 * LDP;        // [128][128]  scaled K tile -> phi
    float* Vs  = Xs + 128 * 128;        // [128][128]  V tile
    float* h_s = Vs + 128 * 128;        // [128]

    const int tid = threadIdx.x;
    const int b   = blockIdx.y;
    const int tx  = tid & 15, ty = tid >> 4;
    const int r0  = ty * 8;
    const int c0  = tx * 8;
    const long long vlen = read_vlen(vlens, b, B);

    for (int idx = tid; idx < 128 * 128; idx += 256) {
        int m = idx >> 7, d = idx & 127;
        Pt[d * LDP + m] = proj[idx];
    }

    u64 kvacc[8][4];
    #pragma unroll
    for (int i = 0; i < 8; i++)
        #pragma unroll
        for (int j = 0; j < 4; j++) kvacc[i][j] = 0ull;
    float ksum_loc = 0.0f;

    const int row_base = blockIdx.x * (tiles_per_block * 128);

    for (int t = 0; t < tiles_per_block; t++) {
        const int row0 = row_base + t * 128;
        const float* kp = ks + ((size_t)b * Kdim + row0) * 128;
        const float* vp = vs + ((size_t)b * Kdim + row0) * 128;
        for (int idx = tid; idx < 128 * 128; idx += 256) {
            Xs[idx] = kp[idx] * nrm;
            Vs[idx] = vp[idx];
        }
        __syncthreads();

        if (tid < 128) {
            float s = 0.0f;
            #pragma unroll 4
            for (int dd = 0; dd < 128; dd++) {
                float v = Xs[tid * 128 + ((dd + tid) & 127)];
                s = fmaf(v, v, s);
            }
            h_s[tid] = 0.5f * s;
        }

        // GEMM1: C[r][m] = sum_d Xs[r][d] * Pt[d][m]
        u64 cacc[8][4];
        #pragma unroll
        for (int i = 0; i < 8; i++)
            #pragma unroll
            for (int j = 0; j < 4; j++) cacc[i][j] = 0ull;

        for (int d = 0; d < 128; d++) {
            u64 ap[8];
            #pragma unroll
            for (int i = 0; i < 8; i++) ap[i] = pack2(Xs[(r0 + i) * 128 + d]);
            const ulonglong2* bp = (const ulonglong2*)(Pt + d * LDP + c0);
            ulonglong2 b01 = bp[0], b23 = bp[1];
            #pragma unroll
            for (int i = 0; i < 8; i++) {
                fma2(cacc[i][0], ap[i], b01.x);
                fma2(cacc[i][1], ap[i], b01.y);
                fma2(cacc[i][2], ap[i], b23.x);
                fma2(cacc[i][3], ap[i], b23.y);
            }
        }
        __syncthreads();   // GEMM1 reads of Xs done

        // phi = __expf(C - h)*ISM, masked; store into Xs
        #pragma unroll
        for (int i = 0; i < 8; i++) {
            int r = r0 + i;
            bool valid = ((long long)(row0 + r) < vlen);
            float hr = h_s[r];
            float4 o0, o1; float2 c;
            c = unpack2(cacc[i][0]);
            o0.x = valid ? __expf(c.x - hr) * ISM : 0.0f;
            o0.y = valid ? __expf(c.y - hr) * ISM : 0.0f;
            c = unpack2(cacc[i][1]);
            o0.z = valid ? __expf(c.x - hr) * ISM : 0.0f;
            o0.w = valid ? __expf(c.y - hr) * ISM : 0.0f;
            c = unpack2(cacc[i][2]);
            o1.x = valid ? __expf(c.x - hr) * ISM : 0.0f;
            o1.y = valid ? __expf(c.y - hr) * ISM : 0.0f;
            c = unpack2(cacc[i][3]);
            o1.z = valid ? __expf(c.x - hr) * ISM : 0.0f;
            o1.w = valid ? __expf(c.y - hr) * ISM : 0.0f;
            *(float4*)(Xs + r * 128 + c0)     = o0;
            *(float4*)(Xs + r * 128 + c0 + 4) = o1;
        }
        __syncthreads();

        // GEMM2: KV[m][v] += sum_r phi[r][m] * Vs[r][v]
        for (int r = 0; r < 128; r++) {
            float4 a03 = *(const float4*)(Xs + r * 128 + r0);
            float4 a47 = *(const float4*)(Xs + r * 128 + r0 + 4);
            u64 ap[8];
            ap[0] = pack2(a03.x); ap[1] = pack2(a03.y);
            ap[2] = pack2(a03.z); ap[3] = pack2(a03.w);
            ap[4] = pack2(a47.x); ap[5] = pack2(a47.y);
            ap[6] = pack2(a47.z); ap[7] = pack2(a47.w);
            const ulonglong2* bp = (const ulonglong2*)(Vs + r * 128 + c0);
            ulonglong2 b01 = bp[0], b23 = bp[1];
            #pragma unroll
            for (int i = 0; i < 8; i++) {
                fma2(kvacc[i][0], ap[i], b01.x);
                fma2(kvacc[i][1], ap[i], b01.y);
                fma2(kvacc[i][2], ap[i], b23.x);
                fma2(kvacc[i][3], ap[i], b23.y);
            }
        }

        if (tid < 128) {
            float s = 0.0f;
            #pragma unroll 4
            for (int r = 0; r < 128; r++) s += Xs[r * 128 + tid];
            ksum_loc += s;
        }
        __syncthreads();
    }

    float* kvb = g_kv + b * 128 * 128;
    #pragma unroll
    for (int i = 0; i < 8; i++) {
        int m = r0 + i;
        #pragma unroll
        for (int j = 0; j < 4; j++) {
            float2 c = unpack2(kvacc[i][j]);
            atomicAdd(kvb + m * 128 + c0 + j * 2,     c.x);
            atomicAdd(kvb + m * 128 + c0 + j * 2 + 1, c.y);
        }
    }
    if (tid < 128) atomicAdd(g_ksum + b * 128 + tid, ksum_loc);
}

// ---------------------------------------------------------------------------
// Kernel 2: out[r][v] = (phi_q @ KV)[r][v] / max(phi_q . ksum, EPS)
// ---------------------------------------------------------------------------
__global__ void __launch_bounds__(256, 1)
out_kernel(const float* __restrict__ qs, const float* __restrict__ proj,
           float* __restrict__ out, int Qdim, float nrm)
{
    extern __shared__ float smem[];
    float* Pt     = smem;
    float* Xs     = Pt + 128 * LDP;
    float* KVs    = Xs + 128 * 128;
    float* ksum_s = KVs + 128 * 128;
    float* h_s    = ksum_s + 128;
    float* den_s  = h_s + 128;

    const int tid = threadIdx.x;
    const int b   = blockIdx.y;
    const int tx  = tid & 15, ty = tid >> 4;
    const int r0  = ty * 8;
    const int c0  = tx * 8;
    const int row0 = blockIdx.x * 128;

    for (int idx = tid; idx < 128 * 128; idx += 256) {
        int m = idx >> 7, d = idx & 127;
        Pt[d * LDP + m] = proj[idx];
        KVs[idx] = g_kv[b * 128 * 128 + idx];
    }
    if (tid < 128) ksum_s[tid] = g_ksum[b * 128 + tid];

    const float* qp = qs + ((size_t)b * Qdim + row0) * 128;
    for (int idx = tid; idx < 128 * 128; idx += 256)
        Xs[idx] = qp[idx] * nrm;
    __syncthreads();

    if (tid < 128) {
        float s = 0.0f;
        #pragma unroll 4
        for (int dd = 0; dd < 128; dd++) {
            float v = Xs[tid * 128 + ((dd + tid) & 127)];
            s = fmaf(v, v, s);
        }
        h_s[tid] = 0.5f * s;
    }

    // GEMM1
    u64 cacc[8][4];
    #pragma unroll
    for (int i = 0; i < 8; i++)
        #pragma unroll
        for (int j = 0; j < 4; j++) cacc[i][j] = 0ull;

    for (int d = 0; d < 128; d++) {
        u64 ap[8];
        #pragma unroll
        for (int i = 0; i < 8; i++) ap[i] = pack2(Xs[(r0 + i) * 128 + d]);
        const ulonglong2* bp = (const ulonglong2*)(Pt + d * LDP + c0);
        ulonglong2 b01 = bp[0], b23 = bp[1];
        #pragma unroll
        for (int i = 0; i < 8; i++) {
            fma2(cacc[i][0], ap[i], b01.x);
            fma2(cacc[i][1], ap[i], b01.y);
            fma2(cacc[i][2], ap[i], b23.x);
            fma2(cacc[i][3], ap[i], b23.y);
        }
    }
    __syncthreads();

    #pragma unroll
    for (int i = 0; i < 8; i++) {
        int r = r0 + i;
        float hr = h_s[r];
        float4 o0, o1; float2 c;
        c = unpack2(cacc[i][0]); o0.x = __expf(c.x - hr) * ISM; o0.y = __expf(c.y - hr) * ISM;
        c = unpack2(cacc[i][1]); o0.z = __expf(c.x - hr) * ISM; o0.w = __expf(c.y - hr) * ISM;
        c = unpack2(cacc[i][2]); o1.x = __expf(c.x - hr) * ISM; o1.y = __expf(c.y - hr) * ISM;
        c = unpack2(cacc[i][3]); o1.z = __expf(c.x - hr) * ISM; o1.w = __expf(c.y - hr) * ISM;
        *(float4*)(Xs + r * 128 + c0)     = o0;
        *(float4*)(Xs + r * 128 + c0 + 4) = o1;
    }
    __syncthreads();

    // den[r] = sum_m phi[r][m] * ksum[m]
    if (tid < 128) {
        float s = 0.0f;
        #pragma unroll 4
        for (int mm = 0; mm < 128; mm++) {
            int m = (mm + tid) & 127;
            s = fmaf(Xs[tid * 128 + m], ksum_s[m], s);
        }
        den_s[tid] = fmaxf(s, EPS_F);
    }

    // GEMM3: O[r][v] = sum_m phi[r][m] * KVs[m][v]
    u64 oacc[8][4];
    #pragma unroll
    for (int i = 0; i < 8; i++)
        #pragma unroll
        for (int j = 0; j < 4; j++) oacc[i][j] = 0ull;

    for (int m = 0; m < 128; m++) {
        u64 ap[8];
        #pragma unroll
        for (int i = 0; i < 8; i++) ap[i] = pack2(Xs[(r0 + i) * 128 + m]);
        const ulonglong2* bp = (const ulonglong2*)(KVs + m * 128 + c0);
        ulonglong2 b01 = bp[0], b23 = bp[1];
        #pragma unroll
        for (int i = 0; i < 8; i++) {
            fma2(oacc[i][0], ap[i], b01.x);
            fma2(oacc[i][1], ap[i], b01.y);
            fma2(oacc[i][2], ap[i], b23.x);
            fma2(oacc[i][3], ap[i], b23.y);
        }
    }
    __syncthreads();

    #pragma unroll
    for (int i = 0; i < 8; i++) {
        int r = r0 + i;
        float inv = 1.0f / den_s[r];
        float4 o0, o1; float2 c;
        c = unpack2(oacc[i][0]); o0.x = c.x * inv; o0.y = c.y * inv;
        c = unpack2(oacc[i][1]); o0.z = c.x * inv; o0.w = c.y * inv;
        c = unpack2(oacc[i][2]); o1.x = c.x * inv; o1.y = c.y * inv;
        c = unpack2(oacc[i][3]); o1.z = c.x * inv; o1.w = c.y * inv;
        float* op = out + ((size_t)b * Qdim + row0 + r) * 128 + c0;
        *(float4*)op       = o0;
        *(float4*)(op + 4) = o1;
    }
}

extern "C" void kernel_launch(void* const* d_in, const int* in_sizes, int n_in,
                              void* d_out, int out_size)
{
    const float* qs    = (const float*)d_in[0];
    const float* ks    = (const float*)d_in[1];
    const float* vs    = (const float*)d_in[2];
    const float* proj  = (const float*)d_in[3];
    const void*  vlens = (const void*)d_in[4];

    const int B = in_sizes[4];
    const int D = 128;
    const int Q = in_sizes[0] / (B * D);
    const int K = in_sizes[1] / (B * D);
    const float nrm = 1.0f / powf((float)D, 0.25f);

    const size_t smem1 = (size_t)(128 * LDP + 2 * 128 * 128 + 128) * sizeof(float);
    const size_t smem2 = (size_t)(128 * LDP + 2 * 128 * 128 + 3 * 128) * sizeof(float);
    cudaFuncSetAttribute(kv_kernel,  cudaFuncAttributeMaxDynamicSharedMemorySize, (int)smem1);
    cudaFuncSetAttribute(out_kernel, cudaFuncAttributeMaxDynamicSharedMemorySize, (int)smem2);

    zero_kernel<<<(MAXB * 128 * 128 + 255) / 256, 256>>>();

    const int TPB = 4;  // 512 K-rows per block -> 128 CTAs
    dim3 g1(K / (TPB * 128), B);
    kv_kernel<<<g1, 256, smem1>>>(ks, vs, proj, vlens, K, TPB, nrm, B);

    dim3 g2(Q / 128, B);
    out_kernel<<<g2, 256, smem2>>>(qs, proj, (float*)d_out, Q, nrm);
}